// round 3
// baseline (speedup 1.0000x reference)
#include <cuda_runtime.h>
#include <math.h>

#define NRR 512
#define NAA 512
#define MAXG 4096
#define TS 16          // tile size (pixels per side)

// Per-gaussian precomputed params (device globals; no allocs).
__device__ float4 g_p0[MAXG];   // (rc, cc, A, B)  exp term = exp2(A dr^2 + B dr dc + C dc^2)
__device__ float4 g_p1[MAXG];   // (C, w, -, -)
__device__ float4 g_bb[MAXG];   // (rc, cc, er, ec) cull record

__global__ void prep_kernel(const float* __restrict__ pos,
                            const float* __restrict__ cov,
                            const float* __restrict__ inten, int N)
{
    int n = blockIdx.x * blockDim.x + threadIdx.x;
    if (n >= N) return;

    const float cb  = 0.8660254037844387f;   // cos(30deg)
    const float sb  = 0.5f;                  // sin(30deg)
    const float RCc = 5773.502691896258f;    // ALT/cos(beta)
    const float RPY = -2886.7513459481287f;  // radar pos y
    const float RPZ = 5000.0f;
    const float L2E = 1.4426950408889634f;

    float dx = pos[n*3+0];
    float dy = pos[n*3+1] - RPY;
    float dz = pos[n*3+2] - RPZ;

    float Xr = dx;
    float Yr = -cb*dy - sb*dz;
    float Zr =  sb*dy - cb*dz;

    float Rmin = sqrtf(Yr*Yr + Zr*Zr + 1e-12f);
    float rc = Rmin + 256.0f - RCc;
    float cc = Xr + 256.0f;
    float u1 = Yr / Rmin;
    float u2 = Zr / Rmin;

    const float* S = cov + n*9;
    float S00=S[0], S01=S[1], S02=S[2], S11=S[4], S12=S[5], S22=S[8];

    float c10 = -cb*S01 - sb*S02;
    float c20 =  sb*S01 - cb*S02;
    float c11 = cb*cb*S11 + 2.0f*cb*sb*S12 + sb*sb*S22;
    float c12 = cb*sb*(S22 - S11) + (cb*cb - sb*sb)*S12;
    float c22 = sb*sb*S11 - 2.0f*sb*cb*S12 + cb*cb*S22;

    float a  = u1*u1*c11 + 2.0f*u1*u2*c12 + u2*u2*c22 + 1e-4f;
    float b  = u1*c10 + u2*c20;
    float d2 = S00 + 1e-4f;

    float det = a*d2 - b*b;
    float inv = 1.0f / det;
    float A = -0.5f * L2E * d2 * inv;
    float B =         L2E * b  * inv;
    float C = -0.5f * L2E * a  * inv;
    float w = inten[n] * 0.15915494309189535f * inv;   // I/(2 pi det)

    // mahal > 210 => fp32 exp underflows to exactly 0 (matches reference)
    const float T = 210.0f;
    float er = sqrtf(T * a);
    float ec = sqrtf(T * d2);

    g_p0[n] = make_float4(rc, cc, A, B);
    g_p1[n] = make_float4(C, w, 0.f, 0.f);
    g_bb[n] = make_float4(rc, cc, er, ec);
}

// 16x16 tile per block, 64 threads: 16 cols x 4 row-groups, 4 rows/thread (stride 4).
__global__ __launch_bounds__(64) void render_kernel(float* __restrict__ out, int N)
{
    __shared__ int sIdx[1024];
    __shared__ int warpTot[2];
    __shared__ int sCount;

    const int tid  = threadIdx.x;
    const int lane = tid & 31;
    const int wid  = tid >> 5;
    const int tx   = tid & 15;      // column within tile
    const int ty   = tid >> 4;      // row group 0..3 (rows ty + 4k)

    const int   col  = blockIdx.x * TS + tx;
    const int   rowb = blockIdx.y * TS;
    const float colf = (float)col;
    const float rf0  = (float)(rowb + ty);
    const float r0   = (float)rowb;
    const float c0   = (float)(blockIdx.x * TS);

    float acc0 = 0.f, acc1 = 0.f, acc2 = 0.f, acc3 = 0.f;

    for (int base = 0; base < N; base += 1024) {
        const int chunkN = min(1024, N - base);

        // ---- cull: interleaved coalesced (gid = base + tid + 64*j) ----
        unsigned msk = 0; int cnt = 0;
        #pragma unroll 4
        for (int j = 0; j < 16; j++) {
            int g = tid + 64*j;
            bool ok = false;
            if (g < chunkN) {
                float4 bb = g_bb[base + g];
                ok = (bb.x + bb.z >= r0) && (bb.x - bb.z <= r0 + (TS-1)) &&
                     (bb.y + bb.w >= c0) && (bb.y - bb.w <= c0 + (TS-1));
            }
            if (ok) { msk |= (1u << j); cnt++; }
        }
        // warp scan + 2-warp combine
        int inc = cnt;
        #pragma unroll
        for (int d = 1; d < 32; d <<= 1) {
            int v = __shfl_up_sync(0xffffffffu, inc, d);
            if (lane >= d) inc += v;
        }
        if (lane == 31) warpTot[wid] = inc;
        __syncthreads();
        int woff = (wid == 1) ? warpTot[0] : 0;
        if (tid == 0) sCount = 0;
        __syncthreads();
        if (tid == 0) sCount = warpTot[0] + warpTot[1];
        int off = woff + inc - cnt;
        #pragma unroll 4
        for (int j = 0; j < 16; j++)
            if (msk & (1u << j)) sIdx[off++] = base + tid + 64*j;
        __syncthreads();

        // ---- splat survivors: 4 rows per thread ----
        const int M = sCount;
        #pragma unroll 2
        for (int i = 0; i < M; i++) {
            const int g = sIdx[i];
            const float4 p0 = g_p0[g];    // uniform address -> broadcast, L1-hit
            const float4 p1 = g_p1[g];

            float dc  = colf - p0.y;
            float Bdc = p0.w * dc;
            float Cq  = p1.x * dc * dc;
            float drb = rf0 - p0.x;
            float A   = p0.z;
            float w   = p1.y;

            float dr0 = drb;
            float dr1 = drb + 4.0f;
            float dr2 = drb + 8.0f;
            float dr3 = drb + 12.0f;

            float t0 = fmaf(A, dr0, Bdc);
            float t1 = fmaf(A, dr1, Bdc);
            float t2 = fmaf(A, dr2, Bdc);
            float t3 = fmaf(A, dr3, Bdc);

            float m0 = fmaf(t0, dr0, Cq);
            float m1 = fmaf(t1, dr1, Cq);
            float m2 = fmaf(t2, dr2, Cq);
            float m3 = fmaf(t3, dr3, Cq);

            float e0, e1, e2, e3;
            asm("ex2.approx.ftz.f32 %0, %1;" : "=f"(e0) : "f"(m0));
            asm("ex2.approx.ftz.f32 %0, %1;" : "=f"(e1) : "f"(m1));
            asm("ex2.approx.ftz.f32 %0, %1;" : "=f"(e2) : "f"(m2));
            asm("ex2.approx.ftz.f32 %0, %1;" : "=f"(e3) : "f"(m3));

            acc0 = fmaf(w, e0, acc0);
            acc1 = fmaf(w, e1, acc1);
            acc2 = fmaf(w, e2, acc2);
            acc3 = fmaf(w, e3, acc3);
        }
        __syncthreads();
    }

    out[(rowb + ty     ) * NAA + col] = acc0;
    out[(rowb + ty + 4 ) * NAA + col] = acc1;
    out[(rowb + ty + 8 ) * NAA + col] = acc2;
    out[(rowb + ty + 12) * NAA + col] = acc3;
}

extern "C" void kernel_launch(void* const* d_in, const int* in_sizes, int n_in,
                              void* d_out, int out_size)
{
    const float* pos   = (const float*)d_in[0];
    const float* cov   = (const float*)d_in[1];
    const float* inten = (const float*)d_in[2];
    float* out = (float*)d_out;

    int N = in_sizes[2];          // N_GAUSS
    if (N > MAXG) N = MAXG;

    prep_kernel<<<(N + 255) / 256, 256>>>(pos, cov, inten, N);

    dim3 grd(NAA / TS, NRR / TS);
    render_kernel<<<grd, 64>>>(out, N);
}

// round 4
// speedup vs baseline: 1.2411x; 1.2411x over previous
#include <cuda_runtime.h>
#include <math.h>

#define NRR 512
#define NAA 512
#define MAXG 4096
#define KC 4            // gaussian chunks (parallel balance factor)

// Per-gaussian params (device globals; no allocs).
__device__ float4 g_p0[MAXG];            // (rc, cc, A, B):  exp2(A dr^2 + B dr dc + C dc^2)
__device__ float4 g_p1[MAXG];            // (C, w, -, -)
__device__ float4 g_bb[MAXG];            // (rc, cc, er, ec) cull record
__device__ float  g_part[KC][NRR*NAA];   // per-chunk partial images (exclusive writes)

__global__ void prep_kernel(const float* __restrict__ pos,
                            const float* __restrict__ cov,
                            const float* __restrict__ inten, int N)
{
    int n = blockIdx.x * blockDim.x + threadIdx.x;
    if (n >= N) return;

    const float cb  = 0.8660254037844387f;   // cos(30deg)
    const float sb  = 0.5f;                  // sin(30deg)
    const float RCc = 5773.502691896258f;    // ALT/cos(beta)
    const float RPY = -2886.7513459481287f;  // radar pos y
    const float RPZ = 5000.0f;
    const float L2E = 1.4426950408889634f;

    float dx = pos[n*3+0];
    float dy = pos[n*3+1] - RPY;
    float dz = pos[n*3+2] - RPZ;

    float Xr = dx;
    float Yr = -cb*dy - sb*dz;
    float Zr =  sb*dy - cb*dz;

    float Rmin = sqrtf(Yr*Yr + Zr*Zr + 1e-12f);
    float rc = Rmin + 256.0f - RCc;
    float cc = Xr + 256.0f;
    float u1 = Yr / Rmin;
    float u2 = Zr / Rmin;

    const float* S = cov + n*9;
    float S00=S[0], S01=S[1], S02=S[2], S11=S[4], S12=S[5], S22=S[8];

    float c10 = -cb*S01 - sb*S02;
    float c20 =  sb*S01 - cb*S02;
    float c11 = cb*cb*S11 + 2.0f*cb*sb*S12 + sb*sb*S22;
    float c12 = cb*sb*(S22 - S11) + (cb*cb - sb*sb)*S12;
    float c22 = sb*sb*S11 - 2.0f*sb*cb*S12 + cb*cb*S22;

    float a  = u1*u1*c11 + 2.0f*u1*u2*c12 + u2*u2*c22 + 1e-4f;
    float b  = u1*c10 + u2*c20;
    float d2 = S00 + 1e-4f;

    float det = a*d2 - b*b;
    float inv = 1.0f / det;
    float A = -0.5f * L2E * d2 * inv;
    float B =         L2E * b  * inv;
    float C = -0.5f * L2E * a  * inv;
    float w = inten[n] * 0.15915494309189535f * inv;

    // mahal > 210 => fp32 exp underflows to exactly 0 (matches reference)
    const float T = 210.0f;
    float er = sqrtf(T * a);
    float ec = sqrtf(T * d2);

    g_p0[n] = make_float4(rc, cc, A, B);
    g_p1[n] = make_float4(C, w, 0.f, 0.f);
    g_bb[n] = make_float4(rc, cc, er, ec);
}

// 32x32 tile per (blockIdx.x, blockIdx.y); gaussian chunk = blockIdx.z.
// 256 threads: 32 cols x 8 row-groups, 4 rows/thread (stride 8).
__global__ __launch_bounds__(256) void render_kernel(int N)
{
    __shared__ int sIdx[256];
    __shared__ int warpTot[8];
    __shared__ int warpOff[8];
    __shared__ int sCount;

    const int tid  = threadIdx.x;
    const int lane = tid & 31;
    const int wid  = tid >> 5;
    const int tx   = tid & 31;
    const int ty   = tid >> 5;

    const int   chunk = blockIdx.z;
    const int   cbeg  = (chunk * N) / KC;
    const int   cend  = ((chunk + 1) * N) / KC;

    const int   col  = blockIdx.x * 32 + tx;
    const int   rowb = blockIdx.y * 32;
    const float colf = (float)col;
    const float rf0  = (float)(rowb + ty);
    const float r0   = (float)rowb;
    const float c0   = (float)(blockIdx.x * 32);

    // ---- cull: one gaussian per thread ----
    const int g = cbeg + tid;
    bool ok = false;
    if (g < cend) {
        float4 bb = g_bb[g];
        ok = (bb.x + bb.z >= r0) && (bb.x - bb.z <= r0 + 31.0f) &&
             (bb.y + bb.w >= c0) && (bb.y - bb.w <= c0 + 31.0f);
    }
    unsigned bal = __ballot_sync(0xffffffffu, ok);
    int wcnt = __popc(bal);
    if (lane == 0) warpTot[wid] = wcnt;
    __syncthreads();
    if (tid == 0) {
        int s = 0;
        #pragma unroll
        for (int w2 = 0; w2 < 8; w2++) { warpOff[w2] = s; s += warpTot[w2]; }
        sCount = s;
    }
    __syncthreads();
    if (ok) {
        int off = warpOff[wid] + __popc(bal & ((1u << lane) - 1u));
        sIdx[off] = g;
    }
    __syncthreads();

    // ---- splat survivors: 4 rows per thread ----
    float acc0 = 0.f, acc1 = 0.f, acc2 = 0.f, acc3 = 0.f;
    const int M = sCount;
    #pragma unroll 2
    for (int i = 0; i < M; i++) {
        const int gi = sIdx[i];
        const float4 p0 = g_p0[gi];   // uniform address -> broadcast
        const float4 p1 = g_p1[gi];

        float dc  = colf - p0.y;
        float Bdc = p0.w * dc;
        float Cq  = p1.x * dc * dc;
        float drb = rf0 - p0.x;
        float A   = p0.z;
        float w   = p1.y;

        float dr0 = drb;
        float dr1 = drb + 8.0f;
        float dr2 = drb + 16.0f;
        float dr3 = drb + 24.0f;

        float t0 = fmaf(A, dr0, Bdc);
        float t1 = fmaf(A, dr1, Bdc);
        float t2 = fmaf(A, dr2, Bdc);
        float t3 = fmaf(A, dr3, Bdc);

        float m0 = fmaf(t0, dr0, Cq);
        float m1 = fmaf(t1, dr1, Cq);
        float m2 = fmaf(t2, dr2, Cq);
        float m3 = fmaf(t3, dr3, Cq);

        float e0, e1, e2, e3;
        asm("ex2.approx.ftz.f32 %0, %1;" : "=f"(e0) : "f"(m0));
        asm("ex2.approx.ftz.f32 %0, %1;" : "=f"(e1) : "f"(m1));
        asm("ex2.approx.ftz.f32 %0, %1;" : "=f"(e2) : "f"(m2));
        asm("ex2.approx.ftz.f32 %0, %1;" : "=f"(e3) : "f"(m3));

        acc0 = fmaf(w, e0, acc0);
        acc1 = fmaf(w, e1, acc1);
        acc2 = fmaf(w, e2, acc2);
        acc3 = fmaf(w, e3, acc3);
    }

    float* dst = g_part[chunk];
    dst[(rowb + ty      ) * NAA + col] = acc0;
    dst[(rowb + ty +  8 ) * NAA + col] = acc1;
    dst[(rowb + ty + 16 ) * NAA + col] = acc2;
    dst[(rowb + ty + 24 ) * NAA + col] = acc3;
}

// Sum the KC partial images (vectorized float4).
__global__ __launch_bounds__(256) void reduce_kernel(float* __restrict__ out)
{
    int i = blockIdx.x * blockDim.x + threadIdx.x;   // float4 index
    const float4* p0 = (const float4*)g_part[0];
    const float4* p1 = (const float4*)g_part[1];
    const float4* p2 = (const float4*)g_part[2];
    const float4* p3 = (const float4*)g_part[3];
    float4 a = p0[i], b = p1[i], c = p2[i], d = p3[i];
    float4 r;
    r.x = (a.x + b.x) + (c.x + d.x);
    r.y = (a.y + b.y) + (c.y + d.y);
    r.z = (a.z + b.z) + (c.z + d.z);
    r.w = (a.w + b.w) + (c.w + d.w);
    ((float4*)out)[i] = r;
}

extern "C" void kernel_launch(void* const* d_in, const int* in_sizes, int n_in,
                              void* d_out, int out_size)
{
    const float* pos   = (const float*)d_in[0];
    const float* cov   = (const float*)d_in[1];
    const float* inten = (const float*)d_in[2];
    float* out = (float*)d_out;

    int N = in_sizes[2];          // N_GAUSS
    if (N > MAXG) N = MAXG;

    prep_kernel<<<(N + 255) / 256, 256>>>(pos, cov, inten, N);

    dim3 grd(NAA / 32, NRR / 32, KC);
    render_kernel<<<grd, 256>>>(N);

    reduce_kernel<<<(NRR * NAA / 4) / 256, 256>>>(out);
}

// round 5
// speedup vs baseline: 1.6896x; 1.3613x over previous
#include <cuda_runtime.h>
#include <math.h>

#define NRR 512
#define NAA 512
#define KC 4               // gaussian chunks per tile (balance factor)
#define NTILES 256         // 16x16 tiles of 32x32 px

// Scratch (device globals; no allocs).
__device__ float g_part[KC][NRR * NAA];   // per-chunk partial images (exclusive writes)
__device__ int   g_tick[NTILES];          // per-tile completion tickets (self-resetting)

// Single fused kernel: prep + cull + splat + tree-reduce.
// Block = (tile x, tile y, chunk z). 256 threads: 32 cols x 8 row-groups, 4 rows/thread.
__global__ __launch_bounds__(256) void sar_kernel(
    const float* __restrict__ pos,
    const float* __restrict__ cov,
    const float* __restrict__ inten,
    float* __restrict__ out, int N)
{
    __shared__ float4 sP0[256];       // (rc, cc, A, B)
    __shared__ float4 sP1[256];       // (C, w, -, -)
    __shared__ int    warpTot[8];
    __shared__ int    warpOff[8];
    __shared__ int    sCount;
    __shared__ int    sLast;

    const int tid  = threadIdx.x;
    const int lane = tid & 31;
    const int wid  = tid >> 5;
    const int tx   = tid & 31;
    const int ty   = tid >> 5;

    const int chunk  = blockIdx.z;
    const int tileId = blockIdx.y * 16 + blockIdx.x;
    const int cbeg   = (chunk * N) / KC;
    const int cend   = ((chunk + 1) * N) / KC;

    const int   col  = blockIdx.x * 32 + tx;
    const int   rowb = blockIdx.y * 32;
    const float colf = (float)col;
    const float rf0  = (float)(rowb + ty);
    const float r0   = (float)rowb;
    const float c0   = (float)(blockIdx.x * 32);

    const float cbeta = 0.8660254037844387f;   // cos(30deg)
    const float sbeta = 0.5f;                  // sin(30deg)
    const float RCc   = 5773.502691896258f;    // ALT/cos(beta)
    const float RPY   = -2886.7513459481287f;  // radar pos y
    const float RPZ   = 5000.0f;
    const float L2E   = 1.4426950408889634f;

    float acc0 = 0.f, acc1 = 0.f, acc2 = 0.f, acc3 = 0.f;

    for (int base = cbeg; base < cend; base += 256) {
        // ---- fused prep + cull: one gaussian per thread, in registers ----
        const int n = base + tid;
        bool  ok = false;
        float rc = 0.f, cc = 0.f, A = 0.f, B = 0.f, C = 0.f, w = 0.f;
        if (n < cend) {
            float dx = pos[n*3+0];
            float dy = pos[n*3+1] - RPY;
            float dz = pos[n*3+2] - RPZ;

            float Xr = dx;
            float Yr = -cbeta*dy - sbeta*dz;
            float Zr =  sbeta*dy - cbeta*dz;

            float Rmin = sqrtf(Yr*Yr + Zr*Zr + 1e-12f);
            rc = Rmin + 256.0f - RCc;
            cc = Xr + 256.0f;
            float u1 = Yr / Rmin;
            float u2 = Zr / Rmin;

            const float* S = cov + n*9;
            float S00=S[0], S01=S[1], S02=S[2], S11=S[4], S12=S[5], S22=S[8];

            float c10 = -cbeta*S01 - sbeta*S02;
            float c20 =  sbeta*S01 - cbeta*S02;
            float c11 = cbeta*cbeta*S11 + 2.0f*cbeta*sbeta*S12 + sbeta*sbeta*S22;
            float c12 = cbeta*sbeta*(S22 - S11) + (cbeta*cbeta - sbeta*sbeta)*S12;
            float c22 = sbeta*sbeta*S11 - 2.0f*sbeta*cbeta*S12 + cbeta*cbeta*S22;

            float a  = u1*u1*c11 + 2.0f*u1*u2*c12 + u2*u2*c22 + 1e-4f;
            float b  = u1*c10 + u2*c20;
            float d2 = S00 + 1e-4f;

            float det = a*d2 - b*b;
            float inv = 1.0f / det;
            A = -0.5f * L2E * d2 * inv;
            B =         L2E * b  * inv;
            C = -0.5f * L2E * a  * inv;
            w = inten[n] * 0.15915494309189535f * inv;

            // mahal > 210 => fp32 exp underflows to exactly 0 (matches reference)
            const float T = 210.0f;
            float er = sqrtf(T * a);
            float ec = sqrtf(T * d2);

            ok = (rc + er >= r0) && (rc - er <= r0 + 31.0f) &&
                 (cc + ec >= c0) && (cc - ec <= c0 + 31.0f);
        }

        unsigned bal = __ballot_sync(0xffffffffu, ok);
        if (lane == 0) warpTot[wid] = __popc(bal);
        __syncthreads();
        if (tid == 0) {
            int s = 0;
            #pragma unroll
            for (int w2 = 0; w2 < 8; w2++) { warpOff[w2] = s; s += warpTot[w2]; }
            sCount = s;
        }
        __syncthreads();
        if (ok) {
            int off = warpOff[wid] + __popc(bal & ((1u << lane) - 1u));
            sP0[off] = make_float4(rc, cc, A, B);
            sP1[off] = make_float4(C, w, 0.f, 0.f);
        }
        __syncthreads();

        // ---- splat survivors: 4 rows per thread ----
        const int M = sCount;
        #pragma unroll 2
        for (int i = 0; i < M; i++) {
            const float4 p0 = sP0[i];   // uniform -> broadcast LDS
            const float4 p1 = sP1[i];

            float dc  = colf - p0.y;
            float Bdc = p0.w * dc;
            float Cq  = p1.x * dc * dc;
            float drb = rf0 - p0.x;

            float dr0 = drb;
            float dr1 = drb + 8.0f;
            float dr2 = drb + 16.0f;
            float dr3 = drb + 24.0f;

            float t0 = fmaf(p0.z, dr0, Bdc);
            float t1 = fmaf(p0.z, dr1, Bdc);
            float t2 = fmaf(p0.z, dr2, Bdc);
            float t3 = fmaf(p0.z, dr3, Bdc);

            float m0 = fmaf(t0, dr0, Cq);
            float m1 = fmaf(t1, dr1, Cq);
            float m2 = fmaf(t2, dr2, Cq);
            float m3 = fmaf(t3, dr3, Cq);

            float e0, e1, e2, e3;
            asm("ex2.approx.ftz.f32 %0, %1;" : "=f"(e0) : "f"(m0));
            asm("ex2.approx.ftz.f32 %0, %1;" : "=f"(e1) : "f"(m1));
            asm("ex2.approx.ftz.f32 %0, %1;" : "=f"(e2) : "f"(m2));
            asm("ex2.approx.ftz.f32 %0, %1;" : "=f"(e3) : "f"(m3));

            acc0 = fmaf(p1.y, e0, acc0);
            acc1 = fmaf(p1.y, e1, acc1);
            acc2 = fmaf(p1.y, e2, acc2);
            acc3 = fmaf(p1.y, e3, acc3);
        }
        __syncthreads();
    }

    // ---- write partial ----
    const int i0 = (rowb + ty      ) * NAA + col;
    const int i1 = (rowb + ty +  8 ) * NAA + col;
    const int i2 = (rowb + ty + 16 ) * NAA + col;
    const int i3 = (rowb + ty + 24 ) * NAA + col;
    float* dst = g_part[chunk];
    dst[i0] = acc0; dst[i1] = acc1; dst[i2] = acc2; dst[i3] = acc3;

    // ---- last block of this tile reduces (fixed chunk order -> deterministic) ----
    __threadfence();
    __syncthreads();
    if (tid == 0) {
        int old = atomicAdd(&g_tick[tileId], 1);
        sLast = (old == KC - 1) ? 1 : 0;
    }
    __syncthreads();
    if (sLast) {
        out[i0] = ((g_part[0][i0] + g_part[1][i0]) + (g_part[2][i0] + g_part[3][i0]));
        out[i1] = ((g_part[0][i1] + g_part[1][i1]) + (g_part[2][i1] + g_part[3][i1]));
        out[i2] = ((g_part[0][i2] + g_part[1][i2]) + (g_part[2][i2] + g_part[3][i2]));
        out[i3] = ((g_part[0][i3] + g_part[1][i3]) + (g_part[2][i3] + g_part[3][i3]));
        if (tid == 0) g_tick[tileId] = 0;   // self-reset for next graph replay
    }
}

extern "C" void kernel_launch(void* const* d_in, const int* in_sizes, int n_in,
                              void* d_out, int out_size)
{
    const float* pos   = (const float*)d_in[0];
    const float* cov   = (const float*)d_in[1];
    const float* inten = (const float*)d_in[2];
    float* out = (float*)d_out;

    int N = in_sizes[2];   // N_GAUSS

    dim3 grd(NAA / 32, NRR / 32, KC);
    sar_kernel<<<grd, 256>>>(pos, cov, inten, out, N);
}